// round 1
// baseline (speedup 1.0000x reference)
#include <cuda_runtime.h>

#define EPSV 1e-5f
typedef unsigned long long ull;

// ---------- packed f32x2 helpers (sm_103a FFMA2 path, PTX-only) ----------
__device__ __forceinline__ ull pk2(float lo, float hi) {
    ull r; asm("mov.b64 %0, {%1, %2};" : "=l"(r) : "f"(lo), "f"(hi)); return r;
}
__device__ __forceinline__ ull ffma2(ull a, ull b, ull c) {
    ull d; asm("fma.rn.f32x2 %0, %1, %2, %3;" : "=l"(d) : "l"(a), "l"(b), "l"(c)); return d;
}
__device__ __forceinline__ float2 upk2(ull v) {
    float2 r; asm("mov.b64 {%0, %1}, %2;" : "=f"(r.x), "=f"(r.y) : "l"(v)); return r;
}

// ---------- scratch (no allocations allowed) ----------
__device__ float g_p[8 * 128 * 64];     // [b][c][k]   pooled BN(x_h)
__device__ float g_ckT[8 * 256 * 64];   // [b][c][k]   ck transposed (k contiguous)
__device__ float g_cvT[8 * 64 * 256];   // [b][k][c]   cv transposed (c contiguous)

// ============================================================
// Kernel 1: BN(x_h) + 8x8 maxpool -> g_p
// p[b,c,i*8+j] = max_{r,s<8} ( x_h[b,c,i*8+r,j*8+s]*scl + bia )
// scl may be negative -> track min and max, select.
// ============================================================
__global__ __launch_bounds__(256) void pool_kernel(
    const float* __restrict__ x_h,
    const float* __restrict__ gam, const float* __restrict__ bet,
    const float* __restrict__ mu,  const float* __restrict__ var)
{
    int idx = blockIdx.x * 256 + threadIdx.x;      // 65536 total
    int k = idx & 63;
    int c = (idx >> 6) & 127;
    int b = idx >> 13;
    int i = k >> 3, j = k & 7;

    float scl = gam[c] * rsqrtf(var[c] + EPSV);
    float bia = bet[c] - mu[c] * scl;

    const float* base = x_h + ((((b * 128 + c) * 64) + i * 8) * 64) + j * 8;
    float mx = -3.4e38f, mn = 3.4e38f;
#pragma unroll
    for (int r = 0; r < 8; r++) {
        const float4* p4 = (const float4*)(base + r * 64);
        float4 a = p4[0], d = p4[1];
        mx = fmaxf(mx, fmaxf(fmaxf(a.x, a.y), fmaxf(a.z, a.w)));
        mx = fmaxf(mx, fmaxf(fmaxf(d.x, d.y), fmaxf(d.z, d.w)));
        mn = fminf(mn, fminf(fminf(a.x, a.y), fminf(a.z, a.w)));
        mn = fminf(mn, fminf(fminf(d.x, d.y), fminf(d.z, d.w)));
    }
    float sel = (scl >= 0.f) ? mx : mn;
    g_p[idx] = sel * scl + bia;
}

// ============================================================
// Kernel 2: kv[b,o,k] = sum_c W[o,c]*p[b,c,k] + bias[o]
// o<256 -> g_ckT[b][o][k] ; o>=256 -> g_cvT[b][k][o-256]
// grid (og=8, b=8), block 256. dyn smem 64KB.
// ============================================================
__global__ __launch_bounds__(256) void kv_kernel(
    const float* __restrict__ kv_w, const float* __restrict__ kv_b)
{
    extern __shared__ float sm2[];
    float* sW = sm2;            // [64][128] natural layout
    float* sP = sm2 + 8192;     // [128][64]

    int og = blockIdx.x, b = blockIdx.y;
    int t = threadIdx.x;

    const float4* wsrc = (const float4*)(kv_w + og * 64 * 128);
    const float4* psrc = (const float4*)(g_p + b * 8192);
#pragma unroll
    for (int i = 0; i < 8; i++) {
        ((float4*)sW)[t + i * 256] = wsrc[t + i * 256];
        ((float4*)sP)[t + i * 256] = psrc[t + i * 256];
    }
    __syncthreads();

    int ty = t >> 4, tx = t & 15;   // o-group, k-group
    float acc[4][4] = {};
#pragma unroll 4
    for (int c = 0; c < 128; c++) {
        float4 pv = ((const float4*)(sP + c * 64))[tx];
        float w0 = sW[(ty * 4 + 0) * 128 + c];
        float w1 = sW[(ty * 4 + 1) * 128 + c];
        float w2 = sW[(ty * 4 + 2) * 128 + c];
        float w3 = sW[(ty * 4 + 3) * 128 + c];
        acc[0][0] += w0 * pv.x; acc[0][1] += w0 * pv.y; acc[0][2] += w0 * pv.z; acc[0][3] += w0 * pv.w;
        acc[1][0] += w1 * pv.x; acc[1][1] += w1 * pv.y; acc[1][2] += w1 * pv.z; acc[1][3] += w1 * pv.w;
        acc[2][0] += w2 * pv.x; acc[2][1] += w2 * pv.y; acc[2][2] += w2 * pv.z; acc[2][3] += w2 * pv.w;
        acc[3][0] += w3 * pv.x; acc[3][1] += w3 * pv.y; acc[3][2] += w3 * pv.z; acc[3][3] += w3 * pv.w;
    }
#pragma unroll
    for (int i = 0; i < 4; i++) {
        int o = og * 64 + ty * 4 + i;
        float bs = kv_b[o];
#pragma unroll
        for (int j = 0; j < 4; j++) {
            int k = tx * 4 + j;
            float v = acc[i][j] + bs;
            if (o < 256) g_ckT[(b * 256 + o) * 64 + k] = v;
            else         g_cvT[(b * 64 + k) * 256 + (o - 256)] = v;
        }
    }
}

// ============================================================
// Kernel 3: fused BN(x_l) -> logits -> softmax -> out + residual
// grid (256 tiles of 64 positions, b=8), block 256, dyn smem 215296B.
// ============================================================
__global__ __launch_bounds__(256) void main_kernel(
    const float* __restrict__ x_l,
    const float* __restrict__ gam, const float* __restrict__ bet,
    const float* __restrict__ mu,  const float* __restrict__ var,
    const float* __restrict__ reatt,
    float* __restrict__ out)
{
    extern __shared__ float sm[];
    float* s_ck  = sm;            // [c=256][k=64]   64KB
    float* s_xl  = sm + 16384;    // [c=256][n=64]   64KB
    float* s_cv  = sm + 32768;    // [k=64][c=256]   64KB
    float* s_att = sm + 49152;    // [k=64][n=64]    16KB
    float* s_scl = sm + 53248;    // 256
    float* s_bia = sm + 53504;    // 256
    float* s_inv = sm + 53760;    // 64

    const int b   = blockIdx.y;
    const int hw0 = blockIdx.x * 64;
    const int t   = threadIdx.x;

    // ---- Phase 0: stage ck/cv, compute BN scale/bias ----
    const float4* cksrc = (const float4*)(g_ckT + b * 16384);
    const float4* cvsrc = (const float4*)(g_cvT + b * 16384);
#pragma unroll
    for (int i = 0; i < 16; i++) ((float4*)s_ck)[t + i * 256] = cksrc[t + i * 256];
#pragma unroll
    for (int i = 0; i < 16; i++) ((float4*)s_cv)[t + i * 256] = cvsrc[t + i * 256];
    {
        float sc = gam[t] * rsqrtf(var[t] + EPSV);
        s_scl[t] = sc;
        s_bia[t] = bet[t] - mu[t] * sc;
    }
    __syncthreads();

    // ---- Phase 1: load x_l tile + BN -> s_xl ----
    const float4* xsrc = (const float4*)(x_l + (long)b * 256 * 16384 + hw0);
#pragma unroll
    for (int i = 0; i < 16; i++) {
        int e = t + i * 256;          // float4 index in [0,4096)
        int c = e >> 4, n4 = e & 15;
        float4 v = xsrc[(long)c * 4096 + n4];
        float sc = s_scl[c], bi = s_bia[c];
        v.x = v.x * sc + bi; v.y = v.y * sc + bi;
        v.z = v.z * sc + bi; v.w = v.w * sc + bi;
        ((float4*)s_xl)[e] = v;
    }
    __syncthreads();

    // ---- Phase 2: logits[k][n] = sum_c ck[c][k]*xl[c][n]; + reatt, *1/8 ----
    {
        const int ty = t >> 4, tx = t & 15;       // k-group, n-group
        const float4*     ck4 = (const float4*)s_ck;
        const ulonglong2* xl2 = (const ulonglong2*)s_xl;
        ull acc[4][2] = {};
#pragma unroll 4
        for (int c = 0; c < 256; c++) {
            float4 a = ck4[c * 16 + ty];
            ulonglong2 bv = xl2[c * 16 + tx];
            ull a0 = pk2(a.x, a.x), a1 = pk2(a.y, a.y);
            ull a2 = pk2(a.z, a.z), a3 = pk2(a.w, a.w);
            acc[0][0] = ffma2(a0, bv.x, acc[0][0]); acc[0][1] = ffma2(a0, bv.y, acc[0][1]);
            acc[1][0] = ffma2(a1, bv.x, acc[1][0]); acc[1][1] = ffma2(a1, bv.y, acc[1][1]);
            acc[2][0] = ffma2(a2, bv.x, acc[2][0]); acc[2][1] = ffma2(a2, bv.y, acc[2][1]);
            acc[3][0] = ffma2(a3, bv.x, acc[3][0]); acc[3][1] = ffma2(a3, bv.y, acc[3][1]);
        }
#pragma unroll
        for (int kk = 0; kk < 4; kk++) {
            int k = ty * 4 + kk;
            float rk = __ldg(reatt + k);
            float2 p0 = upk2(acc[kk][0]), p1 = upk2(acc[kk][1]);
            float* dst = s_att + k * 64 + tx * 4;
            dst[0] = (p0.x + rk) * 0.125f;
            dst[1] = (p0.y + rk) * 0.125f;
            dst[2] = (p1.x + rk) * 0.125f;
            dst[3] = (p1.y + rk) * 0.125f;
        }
    }
    __syncthreads();

    // ---- Phase 2.5: softmax over k per column n (store exp; defer 1/sum) ----
    if (t < 64) {
        float m = -3.4e38f;
#pragma unroll
        for (int k = 0; k < 64; k++) m = fmaxf(m, s_att[k * 64 + t]);
        float s = 0.f;
#pragma unroll
        for (int k = 0; k < 64; k++) {
            float e = __expf(s_att[k * 64 + t] - m);
            s_att[k * 64 + t] = e;
            s += e;
        }
        s_inv[t] = 1.0f / s;
    }
    __syncthreads();

    // ---- Phase 3: out[c][n] = x_l + (sum_k e[k][n]*cv[k][c]) * inv[n] ----
    {
        const int cg = t >> 2, ng = t & 3;
        const int c0 = cg * 4, n0 = ng * 16;
        ull acc[4][8] = {};
#pragma unroll 2
        for (int k = 0; k < 64; k++) {
            float4 cvv = *(const float4*)(s_cv + (k << 8) + c0);
            const ulonglong2* ap = (const ulonglong2*)(s_att + (k << 6) + n0);
            ulonglong2 q0 = ap[0], q1 = ap[1], q2 = ap[2], q3 = ap[3];
            ull d0 = pk2(cvv.x, cvv.x);
            acc[0][0] = ffma2(d0, q0.x, acc[0][0]); acc[0][1] = ffma2(d0, q0.y, acc[0][1]);
            acc[0][2] = ffma2(d0, q1.x, acc[0][2]); acc[0][3] = ffma2(d0, q1.y, acc[0][3]);
            acc[0][4] = ffma2(d0, q2.x, acc[0][4]); acc[0][5] = ffma2(d0, q2.y, acc[0][5]);
            acc[0][6] = ffma2(d0, q3.x, acc[0][6]); acc[0][7] = ffma2(d0, q3.y, acc[0][7]);
            ull d1 = pk2(cvv.y, cvv.y);
            acc[1][0] = ffma2(d1, q0.x, acc[1][0]); acc[1][1] = ffma2(d1, q0.y, acc[1][1]);
            acc[1][2] = ffma2(d1, q1.x, acc[1][2]); acc[1][3] = ffma2(d1, q1.y, acc[1][3]);
            acc[1][4] = ffma2(d1, q2.x, acc[1][4]); acc[1][5] = ffma2(d1, q2.y, acc[1][5]);
            acc[1][6] = ffma2(d1, q3.x, acc[1][6]); acc[1][7] = ffma2(d1, q3.y, acc[1][7]);
            ull d2 = pk2(cvv.z, cvv.z);
            acc[2][0] = ffma2(d2, q0.x, acc[2][0]); acc[2][1] = ffma2(d2, q0.y, acc[2][1]);
            acc[2][2] = ffma2(d2, q1.x, acc[2][2]); acc[2][3] = ffma2(d2, q1.y, acc[2][3]);
            acc[2][4] = ffma2(d2, q2.x, acc[2][4]); acc[2][5] = ffma2(d2, q2.y, acc[2][5]);
            acc[2][6] = ffma2(d2, q3.x, acc[2][6]); acc[2][7] = ffma2(d2, q3.y, acc[2][7]);
            ull d3 = pk2(cvv.w, cvv.w);
            acc[3][0] = ffma2(d3, q0.x, acc[3][0]); acc[3][1] = ffma2(d3, q0.y, acc[3][1]);
            acc[3][2] = ffma2(d3, q1.x, acc[3][2]); acc[3][3] = ffma2(d3, q1.y, acc[3][3]);
            acc[3][4] = ffma2(d3, q2.x, acc[3][4]); acc[3][5] = ffma2(d3, q2.y, acc[3][5]);
            acc[3][6] = ffma2(d3, q3.x, acc[3][6]); acc[3][7] = ffma2(d3, q3.y, acc[3][7]);
        }
        // epilogue: residual + 1/sum
        long gbase = (long)b * 256 * 16384 + hw0 + n0;
#pragma unroll
        for (int cc = 0; cc < 4; cc++) {
            int c = c0 + cc;
            const float4* xg = (const float4*)(x_l + gbase + (long)c * 16384);
            float4*       og = (float4*)(out + gbase + (long)c * 16384);
#pragma unroll
            for (int q = 0; q < 4; q++) {
                float4 xv = xg[q];
                float2 r0 = upk2(acc[cc][q * 2]);
                float2 r1 = upk2(acc[cc][q * 2 + 1]);
                int nb = n0 + q * 4;
                float4 o;
                o.x = xv.x + r0.x * s_inv[nb + 0];
                o.y = xv.y + r0.y * s_inv[nb + 1];
                o.z = xv.z + r1.x * s_inv[nb + 2];
                o.w = xv.w + r1.y * s_inv[nb + 3];
                og[q] = o;
            }
        }
    }
}

// ============================================================
extern "C" void kernel_launch(void* const* d_in, const int* in_sizes, int n_in,
                              void* d_out, int out_size)
{
    const float* x_h   = (const float*)d_in[0];
    const float* x_l   = (const float*)d_in[1];
    const float* bhg   = (const float*)d_in[2];
    const float* bhb   = (const float*)d_in[3];
    const float* bhm   = (const float*)d_in[4];
    const float* bhv   = (const float*)d_in[5];
    const float* kvw   = (const float*)d_in[6];
    const float* kvb   = (const float*)d_in[7];
    const float* blg   = (const float*)d_in[8];
    const float* blb   = (const float*)d_in[9];
    const float* blm   = (const float*)d_in[10];
    const float* blv   = (const float*)d_in[11];
    const float* reatt = (const float*)d_in[12];
    float* out = (float*)d_out;

    cudaFuncSetAttribute(kv_kernel,   cudaFuncAttributeMaxDynamicSharedMemorySize, 65536);
    cudaFuncSetAttribute(main_kernel, cudaFuncAttributeMaxDynamicSharedMemorySize, 215296);

    pool_kernel<<<256, 256>>>(x_h, bhg, bhb, bhm, bhv);
    kv_kernel<<<dim3(8, 8), 256, 65536>>>(kvw, kvb);
    main_kernel<<<dim3(256, 8), 256, 215296>>>(x_l, blg, blb, blm, blv, reatt, out);
}

// round 2
// speedup vs baseline: 1.0017x; 1.0017x over previous
#include <cuda_runtime.h>

#define EPSV 1e-5f
typedef unsigned long long ull;

// ---------- packed f32x2 helpers (sm_103a FFMA2 path, PTX-only) ----------
__device__ __forceinline__ ull pk2(float lo, float hi) {
    ull r; asm("mov.b64 %0, {%1, %2};" : "=l"(r) : "f"(lo), "f"(hi)); return r;
}
__device__ __forceinline__ ull ffma2(ull a, ull b, ull c) {
    ull d; asm("fma.rn.f32x2 %0, %1, %2, %3;" : "=l"(d) : "l"(a), "l"(b), "l"(c)); return d;
}
__device__ __forceinline__ float2 upk2(ull v) {
    float2 r; asm("mov.b64 {%0, %1}, %2;" : "=f"(r.x), "=f"(r.y) : "l"(v)); return r;
}

// ---------- scratch (no allocations allowed) ----------
__device__ float g_p[8 * 128 * 64];     // [b][c][k]   pooled BN(x_h)
__device__ float g_ckT[8 * 256 * 64];   // [b][c][k]   ck transposed (k contiguous)
__device__ float g_cvT[8 * 64 * 256];   // [b][k][c]   cv transposed (c contiguous)

// ============================================================
// Kernel 1: BN(x_h) + 8x8 maxpool -> g_p
// p[b,c,i*8+j] = max_{r,s<8} ( x_h[b,c,i*8+r,j*8+s]*scl + bia )
// scl may be negative -> track min and max, select.
// ============================================================
__global__ __launch_bounds__(256) void pool_kernel(
    const float* __restrict__ x_h,
    const float* __restrict__ gam, const float* __restrict__ bet,
    const float* __restrict__ mu,  const float* __restrict__ var)
{
    int idx = blockIdx.x * 256 + threadIdx.x;      // 65536 total
    int k = idx & 63;
    int c = (idx >> 6) & 127;
    int b = idx >> 13;
    int i = k >> 3, j = k & 7;

    float scl = gam[c] * rsqrtf(var[c] + EPSV);
    float bia = bet[c] - mu[c] * scl;

    const float* base = x_h + ((((b * 128 + c) * 64) + i * 8) * 64) + j * 8;
    float mx = -3.4e38f, mn = 3.4e38f;
#pragma unroll
    for (int r = 0; r < 8; r++) {
        const float4* p4 = (const float4*)(base + r * 64);
        float4 a = p4[0], d = p4[1];
        mx = fmaxf(mx, fmaxf(fmaxf(a.x, a.y), fmaxf(a.z, a.w)));
        mx = fmaxf(mx, fmaxf(fmaxf(d.x, d.y), fmaxf(d.z, d.w)));
        mn = fminf(mn, fminf(fminf(a.x, a.y), fminf(a.z, a.w)));
        mn = fminf(mn, fminf(fminf(d.x, d.y), fminf(d.z, d.w)));
    }
    float sel = (scl >= 0.f) ? mx : mn;
    g_p[idx] = sel * scl + bia;
}

// ============================================================
// Kernel 2: kv[b,o,k] = sum_c W[o,c]*p[b,c,k] + bias[o]
// o<256 -> g_ckT[b][o][k] ; o>=256 -> g_cvT[b][k][o-256]
// grid (og=8, b=8), block 256. dyn smem 64KB.
// ============================================================
__global__ __launch_bounds__(256) void kv_kernel(
    const float* __restrict__ kv_w, const float* __restrict__ kv_b)
{
    extern __shared__ float sm2[];
    float* sW = sm2;            // [64][128] natural layout
    float* sP = sm2 + 8192;     // [128][64]

    int og = blockIdx.x, b = blockIdx.y;
    int t = threadIdx.x;

    const float4* wsrc = (const float4*)(kv_w + og * 64 * 128);
    const float4* psrc = (const float4*)(g_p + b * 8192);
#pragma unroll
    for (int i = 0; i < 8; i++) {
        ((float4*)sW)[t + i * 256] = wsrc[t + i * 256];
        ((float4*)sP)[t + i * 256] = psrc[t + i * 256];
    }
    __syncthreads();

    int ty = t >> 4, tx = t & 15;   // o-group, k-group
    float acc[4][4] = {};
#pragma unroll 4
    for (int c = 0; c < 128; c++) {
        float4 pv = ((const float4*)(sP + c * 64))[tx];
        float w0 = sW[(ty * 4 + 0) * 128 + c];
        float w1 = sW[(ty * 4 + 1) * 128 + c];
        float w2 = sW[(ty * 4 + 2) * 128 + c];
        float w3 = sW[(ty * 4 + 3) * 128 + c];
        acc[0][0] += w0 * pv.x; acc[0][1] += w0 * pv.y; acc[0][2] += w0 * pv.z; acc[0][3] += w0 * pv.w;
        acc[1][0] += w1 * pv.x; acc[1][1] += w1 * pv.y; acc[1][2] += w1 * pv.z; acc[1][3] += w1 * pv.w;
        acc[2][0] += w2 * pv.x; acc[2][1] += w2 * pv.y; acc[2][2] += w2 * pv.z; acc[2][3] += w2 * pv.w;
        acc[3][0] += w3 * pv.x; acc[3][1] += w3 * pv.y; acc[3][2] += w3 * pv.z; acc[3][3] += w3 * pv.w;
    }
#pragma unroll
    for (int i = 0; i < 4; i++) {
        int o = og * 64 + ty * 4 + i;
        float bs = kv_b[o];
#pragma unroll
        for (int j = 0; j < 4; j++) {
            int k = tx * 4 + j;
            float v = acc[i][j] + bs;
            if (o < 256) g_ckT[(b * 256 + o) * 64 + k] = v;
            else         g_cvT[(b * 64 + k) * 256 + (o - 256)] = v;
        }
    }
}

// ============================================================
// Kernel 3: fused BN(x_l) -> logits -> softmax -> out + residual
// grid (256 tiles of 64 positions, b=8), block 256, dyn smem 215296B.
// ============================================================
__global__ __launch_bounds__(256) void main_kernel(
    const float* __restrict__ x_l,
    const float* __restrict__ gam, const float* __restrict__ bet,
    const float* __restrict__ mu,  const float* __restrict__ var,
    const float* __restrict__ reatt,
    float* __restrict__ out)
{
    extern __shared__ float sm[];
    float* s_ck  = sm;            // [c=256][k=64]   64KB
    float* s_xl  = sm + 16384;    // [c=256][n=64]   64KB
    float* s_cv  = sm + 32768;    // [k=64][c=256]   64KB
    float* s_att = sm + 49152;    // [k=64][n=64]    16KB
    float* s_scl = sm + 53248;    // 256
    float* s_bia = sm + 53504;    // 256
    float* s_inv = sm + 53760;    // 64

    const int b   = blockIdx.y;
    const int hw0 = blockIdx.x * 64;
    const int t   = threadIdx.x;

    // ---- Phase 0: stage ck/cv, compute BN scale/bias ----
    const float4* cksrc = (const float4*)(g_ckT + b * 16384);
    const float4* cvsrc = (const float4*)(g_cvT + b * 16384);
#pragma unroll
    for (int i = 0; i < 16; i++) ((float4*)s_ck)[t + i * 256] = cksrc[t + i * 256];
#pragma unroll
    for (int i = 0; i < 16; i++) ((float4*)s_cv)[t + i * 256] = cvsrc[t + i * 256];
    {
        float sc = gam[t] * rsqrtf(var[t] + EPSV);
        s_scl[t] = sc;
        s_bia[t] = bet[t] - mu[t] * sc;
    }
    __syncthreads();

    // ---- Phase 1: load x_l tile + BN -> s_xl ----
    const float4* xsrc = (const float4*)(x_l + (long)b * 256 * 16384 + hw0);
#pragma unroll
    for (int i = 0; i < 16; i++) {
        int e = t + i * 256;          // float4 index in [0,4096)
        int c = e >> 4, n4 = e & 15;
        float4 v = xsrc[(long)c * 4096 + n4];
        float sc = s_scl[c], bi = s_bia[c];
        v.x = v.x * sc + bi; v.y = v.y * sc + bi;
        v.z = v.z * sc + bi; v.w = v.w * sc + bi;
        ((float4*)s_xl)[e] = v;
    }
    __syncthreads();

    // ---- Phase 2: logits[k][n] = sum_c ck[c][k]*xl[c][n]; + reatt, *1/8 ----
    {
        const int ty = t >> 4, tx = t & 15;       // k-group, n-group
        const float4*     ck4 = (const float4*)s_ck;
        const ulonglong2* xl2 = (const ulonglong2*)s_xl;
        ull acc[4][2] = {};
#pragma unroll 4
        for (int c = 0; c < 256; c++) {
            float4 a = ck4[c * 16 + ty];
            ulonglong2 bv = xl2[c * 16 + tx];
            ull a0 = pk2(a.x, a.x), a1 = pk2(a.y, a.y);
            ull a2 = pk2(a.z, a.z), a3 = pk2(a.w, a.w);
            acc[0][0] = ffma2(a0, bv.x, acc[0][0]); acc[0][1] = ffma2(a0, bv.y, acc[0][1]);
            acc[1][0] = ffma2(a1, bv.x, acc[1][0]); acc[1][1] = ffma2(a1, bv.y, acc[1][1]);
            acc[2][0] = ffma2(a2, bv.x, acc[2][0]); acc[2][1] = ffma2(a2, bv.y, acc[2][1]);
            acc[3][0] = ffma2(a3, bv.x, acc[3][0]); acc[3][1] = ffma2(a3, bv.y, acc[3][1]);
        }
#pragma unroll
        for (int kk = 0; kk < 4; kk++) {
            int k = ty * 4 + kk;
            float rk = __ldg(reatt + k);
            float2 p0 = upk2(acc[kk][0]), p1 = upk2(acc[kk][1]);
            float* dst = s_att + k * 64 + tx * 4;
            dst[0] = (p0.x + rk) * 0.125f;
            dst[1] = (p0.y + rk) * 0.125f;
            dst[2] = (p1.x + rk) * 0.125f;
            dst[3] = (p1.y + rk) * 0.125f;
        }
    }
    __syncthreads();

    // ---- Phase 2.5: softmax over k per column n (store exp; defer 1/sum) ----
    if (t < 64) {
        float m = -3.4e38f;
#pragma unroll
        for (int k = 0; k < 64; k++) m = fmaxf(m, s_att[k * 64 + t]);
        float s = 0.f;
#pragma unroll
        for (int k = 0; k < 64; k++) {
            float e = __expf(s_att[k * 64 + t] - m);
            s_att[k * 64 + t] = e;
            s += e;
        }
        s_inv[t] = 1.0f / s;
    }
    __syncthreads();

    // ---- Phase 3: out[c][n] = x_l + (sum_k e[k][n]*cv[k][c]) * inv[n] ----
    {
        const int cg = t >> 2, ng = t & 3;
        const int c0 = cg * 4, n0 = ng * 16;
        ull acc[4][8] = {};
#pragma unroll 2
        for (int k = 0; k < 64; k++) {
            float4 cvv = *(const float4*)(s_cv + (k << 8) + c0);
            const ulonglong2* ap = (const ulonglong2*)(s_att + (k << 6) + n0);
            ulonglong2 q0 = ap[0], q1 = ap[1], q2 = ap[2], q3 = ap[3];
            ull d0 = pk2(cvv.x, cvv.x);
            acc[0][0] = ffma2(d0, q0.x, acc[0][0]); acc[0][1] = ffma2(d0, q0.y, acc[0][1]);
            acc[0][2] = ffma2(d0, q1.x, acc[0][2]); acc[0][3] = ffma2(d0, q1.y, acc[0][3]);
            acc[0][4] = ffma2(d0, q2.x, acc[0][4]); acc[0][5] = ffma2(d0, q2.y, acc[0][5]);
            acc[0][6] = ffma2(d0, q3.x, acc[0][6]); acc[0][7] = ffma2(d0, q3.y, acc[0][7]);
            ull d1 = pk2(cvv.y, cvv.y);
            acc[1][0] = ffma2(d1, q0.x, acc[1][0]); acc[1][1] = ffma2(d1, q0.y, acc[1][1]);
            acc[1][2] = ffma2(d1, q1.x, acc[1][2]); acc[1][3] = ffma2(d1, q1.y, acc[1][3]);
            acc[1][4] = ffma2(d1, q2.x, acc[1][4]); acc[1][5] = ffma2(d1, q2.y, acc[1][5]);
            acc[1][6] = ffma2(d1, q3.x, acc[1][6]); acc[1][7] = ffma2(d1, q3.y, acc[1][7]);
            ull d2 = pk2(cvv.z, cvv.z);
            acc[2][0] = ffma2(d2, q0.x, acc[2][0]); acc[2][1] = ffma2(d2, q0.y, acc[2][1]);
            acc[2][2] = ffma2(d2, q1.x, acc[2][2]); acc[2][3] = ffma2(d2, q1.y, acc[2][3]);
            acc[2][4] = ffma2(d2, q2.x, acc[2][4]); acc[2][5] = ffma2(d2, q2.y, acc[2][5]);
            acc[2][6] = ffma2(d2, q3.x, acc[2][6]); acc[2][7] = ffma2(d2, q3.y, acc[2][7]);
            ull d3 = pk2(cvv.w, cvv.w);
            acc[3][0] = ffma2(d3, q0.x, acc[3][0]); acc[3][1] = ffma2(d3, q0.y, acc[3][1]);
            acc[3][2] = ffma2(d3, q1.x, acc[3][2]); acc[3][3] = ffma2(d3, q1.y, acc[3][3]);
            acc[3][4] = ffma2(d3, q2.x, acc[3][4]); acc[3][5] = ffma2(d3, q2.y, acc[3][5]);
            acc[3][6] = ffma2(d3, q3.x, acc[3][6]); acc[3][7] = ffma2(d3, q3.y, acc[3][7]);
        }
        // epilogue: residual + 1/sum
        long gbase = (long)b * 256 * 16384 + hw0 + n0;
#pragma unroll
        for (int cc = 0; cc < 4; cc++) {
            int c = c0 + cc;
            const float4* xg = (const float4*)(x_l + gbase + (long)c * 16384);
            float4*       og = (float4*)(out + gbase + (long)c * 16384);
#pragma unroll
            for (int q = 0; q < 4; q++) {
                float4 xv = xg[q];
                float2 r0 = upk2(acc[cc][q * 2]);
                float2 r1 = upk2(acc[cc][q * 2 + 1]);
                int nb = n0 + q * 4;
                float4 o;
                o.x = xv.x + r0.x * s_inv[nb + 0];
                o.y = xv.y + r0.y * s_inv[nb + 1];
                o.z = xv.z + r1.x * s_inv[nb + 2];
                o.w = xv.w + r1.y * s_inv[nb + 3];
                og[q] = o;
            }
        }
    }
}

// ============================================================
extern "C" void kernel_launch(void* const* d_in, const int* in_sizes, int n_in,
                              void* d_out, int out_size)
{
    const float* x_h   = (const float*)d_in[0];
    const float* x_l   = (const float*)d_in[1];
    const float* bhg   = (const float*)d_in[2];
    const float* bhb   = (const float*)d_in[3];
    const float* bhm   = (const float*)d_in[4];
    const float* bhv   = (const float*)d_in[5];
    const float* kvw   = (const float*)d_in[6];
    const float* kvb   = (const float*)d_in[7];
    const float* blg   = (const float*)d_in[8];
    const float* blb   = (const float*)d_in[9];
    const float* blm   = (const float*)d_in[10];
    const float* blv   = (const float*)d_in[11];
    const float* reatt = (const float*)d_in[12];
    float* out = (float*)d_out;

    cudaFuncSetAttribute(kv_kernel,   cudaFuncAttributeMaxDynamicSharedMemorySize, 65536);
    cudaFuncSetAttribute(main_kernel, cudaFuncAttributeMaxDynamicSharedMemorySize, 215296);

    pool_kernel<<<256, 256>>>(x_h, bhg, bhb, bhm, bhv);
    kv_kernel<<<dim3(8, 8), 256, 65536>>>(kvw, kvb);
    main_kernel<<<dim3(256, 8), 256, 215296>>>(x_l, blg, blb, blm, blv, reatt, out);
}

// round 3
// speedup vs baseline: 1.1145x; 1.1126x over previous
#include <cuda_runtime.h>

#define EPSV 1e-5f
typedef unsigned long long ull;

__device__ __forceinline__ ull pk2(float lo, float hi) {
    ull r; asm("mov.b64 %0, {%1, %2};" : "=l"(r) : "f"(lo), "f"(hi)); return r;
}
__device__ __forceinline__ ull ffma2(ull a, ull b, ull c) {
    ull d; asm("fma.rn.f32x2 %0, %1, %2, %3;" : "=l"(d) : "l"(a), "l"(b), "l"(c)); return d;
}
__device__ __forceinline__ float2 upk2(ull v) {
    float2 r; asm("mov.b64 {%0, %1}, %2;" : "=f"(r.x), "=f"(r.y) : "l"(v)); return r;
}

__device__ float g_p[8 * 128 * 64];
__device__ float g_ckT[8 * 256 * 64];   // [b][c][k]
__device__ float g_cvT[8 * 64 * 256];   // [b][k][c]

// ================= Kernel 1: BN(x_h) + 8x8 maxpool =================
__global__ __launch_bounds__(256) void pool_kernel(
    const float* __restrict__ x_h,
    const float* __restrict__ gam, const float* __restrict__ bet,
    const float* __restrict__ mu,  const float* __restrict__ var)
{
    int idx = blockIdx.x * 256 + threadIdx.x;
    int k = idx & 63, c = (idx >> 6) & 127, b = idx >> 13;
    int i = k >> 3, j = k & 7;
    float scl = gam[c] * rsqrtf(var[c] + EPSV);
    float bia = bet[c] - mu[c] * scl;
    const float* base = x_h + ((((b * 128 + c) * 64) + i * 8) * 64) + j * 8;
    float mx = -3.4e38f, mn = 3.4e38f;
#pragma unroll
    for (int r = 0; r < 8; r++) {
        const float4* p4 = (const float4*)(base + r * 64);
        float4 a = p4[0], d = p4[1];
        mx = fmaxf(mx, fmaxf(fmaxf(a.x, a.y), fmaxf(a.z, a.w)));
        mx = fmaxf(mx, fmaxf(fmaxf(d.x, d.y), fmaxf(d.z, d.w)));
        mn = fminf(mn, fminf(fminf(a.x, a.y), fminf(a.z, a.w)));
        mn = fminf(mn, fminf(fminf(d.x, d.y), fminf(d.z, d.w)));
    }
    g_p[idx] = ((scl >= 0.f) ? mx : mn) * scl + bia;
}

// ================= Kernel 2: 1x1 conv -> ckT / cvT =================
__global__ __launch_bounds__(256) void kv_kernel(
    const float* __restrict__ kv_w, const float* __restrict__ kv_b)
{
    extern __shared__ float sm2[];
    float* sW = sm2;          // [64][128]
    float* sP = sm2 + 8192;   // [128][64]
    int og = blockIdx.x, b = blockIdx.y, t = threadIdx.x;
    const float4* wsrc = (const float4*)(kv_w + og * 64 * 128);
    const float4* psrc = (const float4*)(g_p + b * 8192);
#pragma unroll
    for (int i = 0; i < 8; i++) {
        ((float4*)sW)[t + i * 256] = wsrc[t + i * 256];
        ((float4*)sP)[t + i * 256] = psrc[t + i * 256];
    }
    __syncthreads();
    int ty = t >> 4, tx = t & 15;
    float acc[4][4] = {};
#pragma unroll 4
    for (int c = 0; c < 128; c++) {
        float4 pv = ((const float4*)(sP + c * 64))[tx];
        float w0 = sW[(ty * 4 + 0) * 128 + c];
        float w1 = sW[(ty * 4 + 1) * 128 + c];
        float w2 = sW[(ty * 4 + 2) * 128 + c];
        float w3 = sW[(ty * 4 + 3) * 128 + c];
        acc[0][0] += w0 * pv.x; acc[0][1] += w0 * pv.y; acc[0][2] += w0 * pv.z; acc[0][3] += w0 * pv.w;
        acc[1][0] += w1 * pv.x; acc[1][1] += w1 * pv.y; acc[1][2] += w1 * pv.z; acc[1][3] += w1 * pv.w;
        acc[2][0] += w2 * pv.x; acc[2][1] += w2 * pv.y; acc[2][2] += w2 * pv.z; acc[2][3] += w2 * pv.w;
        acc[3][0] += w3 * pv.x; acc[3][1] += w3 * pv.y; acc[3][2] += w3 * pv.z; acc[3][3] += w3 * pv.w;
    }
#pragma unroll
    for (int i = 0; i < 4; i++) {
        int o = og * 64 + ty * 4 + i;
        float bs = kv_b[o];
#pragma unroll
        for (int j = 0; j < 4; j++) {
            int k = tx * 4 + j;
            float v = acc[i][j] + bs;
            if (o < 256) g_ckT[(b * 256 + o) * 64 + k] = v;
            else         g_cvT[(b * 64 + k) * 256 + (o - 256)] = v;
        }
    }
}

// ================= Kernel 3: persistent fused main =================
// grid 152 (1/SM), block 256, smem 216576B.
__global__ __launch_bounds__(256) void main_kernel(
    const float* __restrict__ x_l,
    const float* __restrict__ gam, const float* __restrict__ bet,
    const float* __restrict__ mu,  const float* __restrict__ var,
    const float* __restrict__ reatt,
    float* __restrict__ out)
{
    extern __shared__ float sm[];
    float* s_ck  = sm;            // ckS [c=256][k=64]  (scaled by scl*0.125)
    float* s_xl  = sm + 16384;    // raw x_l [c=256][n=64]
    float* s_cv  = sm + 32768;    // [k=64][c=256]
    float* s_att = sm + 49152;    // [k=64][n=64]
    float* s_scl = sm + 53248;    // 256
    float* s_bia = sm + 53504;    // 256
    float* s_red = sm + 53760;    // 256
    float* s_kb  = sm + 54016;    // 64
    float* s_inv = sm + 54080;    // 64

    const int t = threadIdx.x;
    const int bid = blockIdx.x;
    // 2048 tiles over 152 blocks: first 72 blocks get 14, rest 13
    const int start = bid * 13 + (bid < 72 ? bid : 72);
    const int cnt   = 13 + (bid < 72 ? 1 : 0);

    { // BN_l scale/bias (same for all batches)
        float sc = gam[t] * rsqrtf(var[t] + EPSV);
        s_scl[t] = sc;
        s_bia[t] = bet[t] - mu[t] * sc;
    }
    { // initial x_l tile (raw)
        int b0 = start >> 8, h0 = (start & 255) << 6;
        const float4* xs = (const float4*)(x_l + (long)b0 * 4194304 + h0);
#pragma unroll
        for (int i = 0; i < 16; i++) {
            int e = t + i * 256;
            ((float4*)s_xl)[e] = xs[(long)(e >> 4) * 4096 + (e & 15)];
        }
    }

    int cur_b = -1;
    for (int g = start; g < start + cnt; ++g) {
        const int b = g >> 8;
        const int hw0 = (g & 255) << 6;

        if (b != cur_b) { // restage ck/cv/kb for new batch
            cur_b = b;
            __syncthreads();
            const float4* cks = (const float4*)(g_ckT + b * 16384);
            const float4* cvs = (const float4*)(g_cvT + b * 16384);
#pragma unroll
            for (int i = 0; i < 16; i++) {
                int e = t + i * 256;
                float4 v = cks[e];
                float f = s_scl[e >> 4] * 0.125f;
                v.x *= f; v.y *= f; v.z *= f; v.w *= f;
                ((float4*)s_ck)[e] = v;
                ((float4*)s_cv)[e] = cvs[e];
            }
            { // kb partials: kb[k] = sum_c ck[c][k]*bia[c]
                int q = t >> 6, k = t & 63;
                const float* base = g_ckT + b * 16384 + k;
                float s = 0.f;
#pragma unroll 8
                for (int c = q * 64; c < q * 64 + 64; c++) s += base[c * 64] * s_bia[c];
                s_red[t] = s;
            }
            __syncthreads();
            if (t < 64)
                s_kb[t] = 0.125f * (s_red[t] + s_red[64 + t] + s_red[128 + t] + s_red[192 + t]
                                    + __ldg(reatt + t));
        }
        __syncthreads();

        // ---- Phase 2: logits[k][n] = sum_c ckS[c][k]*xl_raw[c][n] + kb[k] ----
        {
            const int ty = t >> 4, tx = t & 15;
            const float4*     ck4 = (const float4*)s_ck;
            const ulonglong2* xl2 = (const ulonglong2*)s_xl;
            ull acc[4][2] = {};
#pragma unroll 4
            for (int c = 0; c < 256; c++) {
                float4 a = ck4[c * 16 + ty];
                ulonglong2 bv = xl2[c * 16 + tx];
                ull a0 = pk2(a.x, a.x), a1 = pk2(a.y, a.y);
                ull a2 = pk2(a.z, a.z), a3 = pk2(a.w, a.w);
                acc[0][0] = ffma2(a0, bv.x, acc[0][0]); acc[0][1] = ffma2(a0, bv.y, acc[0][1]);
                acc[1][0] = ffma2(a1, bv.x, acc[1][0]); acc[1][1] = ffma2(a1, bv.y, acc[1][1]);
                acc[2][0] = ffma2(a2, bv.x, acc[2][0]); acc[2][1] = ffma2(a2, bv.y, acc[2][1]);
                acc[3][0] = ffma2(a3, bv.x, acc[3][0]); acc[3][1] = ffma2(a3, bv.y, acc[3][1]);
            }
#pragma unroll
            for (int kk = 0; kk < 4; kk++) {
                int k = ty * 4 + kk;
                float kb = s_kb[k];
                float2 p0 = upk2(acc[kk][0]), p1 = upk2(acc[kk][1]);
                float* dst = s_att + k * 64 + tx * 4;
                dst[0] = p0.x + kb; dst[1] = p0.y + kb;
                dst[2] = p1.x + kb; dst[3] = p1.y + kb;
            }
        }
        __syncthreads();

        // ---- softmax over k, parallel: 4 threads per column ----
        {
            int q = t >> 6, n = t & 63;
            float m = -3.4e38f;
#pragma unroll
            for (int k = q * 16; k < q * 16 + 16; k++) m = fmaxf(m, s_att[k * 64 + n]);
            s_red[t] = m;
            __syncthreads();
            m = fmaxf(fmaxf(s_red[n], s_red[64 + n]), fmaxf(s_red[128 + n], s_red[192 + n]));
            float s = 0.f;
#pragma unroll
            for (int k = q * 16; k < q * 16 + 16; k++) {
                float e = __expf(s_att[k * 64 + n] - m);
                s_att[k * 64 + n] = e;
                s += e;
            }
            __syncthreads();   // all max reads done before overwriting s_red
            s_red[t] = s;
            __syncthreads();
            if (t < 64)
                s_inv[t] = 1.0f / (s_red[t] + s_red[64 + t] + s_red[128 + t] + s_red[192 + t]);
        }
        __syncthreads();

        // ---- prefetch next tile's x_l into registers (hidden under phase 3) ----
        const bool has_next = (g + 1 < start + cnt);
        float4 pf[16];
        if (has_next) {
            int gn = g + 1, bn = gn >> 8, hn = (gn & 255) << 6;
            const float4* xs = (const float4*)(x_l + (long)bn * 4194304 + hn);
#pragma unroll
            for (int i = 0; i < 16; i++) {
                int e = t + i * 256;
                pf[i] = xs[(long)(e >> 4) * 4096 + (e & 15)];
            }
        }

        // ---- Phase 3: out[c][n] = xl_raw + (sum_k e[k][n]*cv[k][c]) * inv[n] ----
        {
            const int cg = t >> 2, ng = t & 3;
            const int c0 = cg * 4, n0 = ng * 16;
            ull acc[4][8] = {};
#pragma unroll 2
            for (int k = 0; k < 64; k++) {
                float4 cvv = *(const float4*)(s_cv + (k << 8) + c0);
                const ulonglong2* ap = (const ulonglong2*)(s_att + (k << 6) + n0);
                ulonglong2 q0 = ap[0], q1 = ap[1], q2 = ap[2], q3 = ap[3];
                ull d0 = pk2(cvv.x, cvv.x);
                acc[0][0] = ffma2(d0, q0.x, acc[0][0]); acc[0][1] = ffma2(d0, q0.y, acc[0][1]);
                acc[0][2] = ffma2(d0, q1.x, acc[0][2]); acc[0][3] = ffma2(d0, q1.y, acc[0][3]);
                acc[0][4] = ffma2(d0, q2.x, acc[0][4]); acc[0][5] = ffma2(d0, q2.y, acc[0][5]);
                acc[0][6] = ffma2(d0, q3.x, acc[0][6]); acc[0][7] = ffma2(d0, q3.y, acc[0][7]);
                ull d1 = pk2(cvv.y, cvv.y);
                acc[1][0] = ffma2(d1, q0.x, acc[1][0]); acc[1][1] = ffma2(d1, q0.y, acc[1][1]);
                acc[1][2] = ffma2(d1, q1.x, acc[1][2]); acc[1][3] = ffma2(d1, q1.y, acc[1][3]);
                acc[1][4] = ffma2(d1, q2.x, acc[1][4]); acc[1][5] = ffma2(d1, q2.y, acc[1][5]);
                acc[1][6] = ffma2(d1, q3.x, acc[1][6]); acc[1][7] = ffma2(d1, q3.y, acc[1][7]);
                ull d2 = pk2(cvv.z, cvv.z);
                acc[2][0] = ffma2(d2, q0.x, acc[2][0]); acc[2][1] = ffma2(d2, q0.y, acc[2][1]);
                acc[2][2] = ffma2(d2, q1.x, acc[2][2]); acc[2][3] = ffma2(d2, q1.y, acc[2][3]);
                acc[2][4] = ffma2(d2, q2.x, acc[2][4]); acc[2][5] = ffma2(d2, q2.y, acc[2][5]);
                acc[2][6] = ffma2(d2, q3.x, acc[2][6]); acc[2][7] = ffma2(d2, q3.y, acc[2][7]);
                ull d3 = pk2(cvv.w, cvv.w);
                acc[3][0] = ffma2(d3, q0.x, acc[3][0]); acc[3][1] = ffma2(d3, q0.y, acc[3][1]);
                acc[3][2] = ffma2(d3, q1.x, acc[3][2]); acc[3][3] = ffma2(d3, q1.y, acc[3][3]);
                acc[3][4] = ffma2(d3, q2.x, acc[3][4]); acc[3][5] = ffma2(d3, q2.y, acc[3][5]);
                acc[3][6] = ffma2(d3, q3.x, acc[3][6]); acc[3][7] = ffma2(d3, q3.y, acc[3][7]);
            }
            long gbase = (long)b * 4194304 + hw0 + n0;
#pragma unroll
            for (int cc = 0; cc < 4; cc++) {
                int c = c0 + cc;
                const float4* xs = (const float4*)(s_xl + c * 64 + n0);
                float4*       og = (float4*)(out + gbase + (long)c * 16384);
#pragma unroll
                for (int q = 0; q < 4; q++) {
                    float4 xv = xs[q];
                    float2 r0 = upk2(acc[cc][q * 2]);
                    float2 r1 = upk2(acc[cc][q * 2 + 1]);
                    int nb = n0 + q * 4;
                    float4 o;
                    o.x = xv.x + r0.x * s_inv[nb + 0];
                    o.y = xv.y + r0.y * s_inv[nb + 1];
                    o.z = xv.z + r1.x * s_inv[nb + 2];
                    o.w = xv.w + r1.y * s_inv[nb + 3];
                    og[q] = o;
                }
            }
        }
        __syncthreads();   // s_xl fully consumed by epilogue
        if (has_next) {
#pragma unroll
            for (int i = 0; i < 16; i++) {
                int e = t + i * 256;
                ((float4*)s_xl)[e] = pf[i];
            }
        }
    }
}

// ============================================================
extern "C" void kernel_launch(void* const* d_in, const int* in_sizes, int n_in,
                              void* d_out, int out_size)
{
    const float* x_h   = (const float*)d_in[0];
    const float* x_l   = (const float*)d_in[1];
    const float* bhg   = (const float*)d_in[2];
    const float* bhb   = (const float*)d_in[3];
    const float* bhm   = (const float*)d_in[4];
    const float* bhv   = (const float*)d_in[5];
    const float* kvw   = (const float*)d_in[6];
    const float* kvb   = (const float*)d_in[7];
    const float* blg   = (const float*)d_in[8];
    const float* blb   = (const float*)d_in[9];
    const float* blm   = (const float*)d_in[10];
    const float* blv   = (const float*)d_in[11];
    const float* reatt = (const float*)d_in[12];
    float* out = (float*)d_out;

    cudaFuncSetAttribute(kv_kernel,   cudaFuncAttributeMaxDynamicSharedMemorySize, 65536);
    cudaFuncSetAttribute(main_kernel, cudaFuncAttributeMaxDynamicSharedMemorySize, 216576);

    pool_kernel<<<256, 256>>>(x_h, bhg, bhb, bhm, bhv);
    kv_kernel<<<dim3(8, 8), 256, 65536>>>(kvw, kvb);
    main_kernel<<<152, 256, 216576>>>(x_l, blg, blb, blm, blv, reatt, out);
}

// round 5
// speedup vs baseline: 1.1146x; 1.0001x over previous
#include <cuda_runtime.h>

#define EPSV 1e-5f
typedef unsigned long long ull;

__device__ __forceinline__ ull pk2(float lo, float hi) {
    ull r; asm("mov.b64 %0, {%1, %2};" : "=l"(r) : "f"(lo), "f"(hi)); return r;
}
__device__ __forceinline__ ull ffma2(ull a, ull b, ull c) {
    ull d; asm("fma.rn.f32x2 %0, %1, %2, %3;" : "=l"(d) : "l"(a), "l"(b), "l"(c)); return d;
}
__device__ __forceinline__ float2 upk2(ull v) {
    float2 r; asm("mov.b64 {%0, %1}, %2;" : "=f"(r.x), "=f"(r.y) : "l"(v)); return r;
}

__device__ float g_p[8 * 128 * 64];
__device__ float g_ckT[8 * 256 * 64];   // [b][c][k]
__device__ float g_cvT[8 * 64 * 256];   // [b][k][c]

// ================= Kernel 1: BN(x_h) + 8x8 maxpool =================
__global__ __launch_bounds__(256) void pool_kernel(
    const float* __restrict__ x_h,
    const float* __restrict__ gam, const float* __restrict__ bet,
    const float* __restrict__ mu,  const float* __restrict__ var)
{
    int idx = blockIdx.x * 256 + threadIdx.x;
    int k = idx & 63, c = (idx >> 6) & 127, b = idx >> 13;
    int i = k >> 3, j = k & 7;
    float scl = gam[c] * rsqrtf(var[c] + EPSV);
    float bia = bet[c] - mu[c] * scl;
    const float* base = x_h + ((((b * 128 + c) * 64) + i * 8) * 64) + j * 8;
    float mx = -3.4e38f, mn = 3.4e38f;
#pragma unroll
    for (int r = 0; r < 8; r++) {
        const float4* p4 = (const float4*)(base + r * 64);
        float4 a = p4[0], d = p4[1];
        mx = fmaxf(mx, fmaxf(fmaxf(a.x, a.y), fmaxf(a.z, a.w)));
        mx = fmaxf(mx, fmaxf(fmaxf(d.x, d.y), fmaxf(d.z, d.w)));
        mn = fminf(mn, fminf(fminf(a.x, a.y), fminf(a.z, a.w)));
        mn = fminf(mn, fminf(fminf(d.x, d.y), fminf(d.z, d.w)));
    }
    g_p[idx] = ((scl >= 0.f) ? mx : mn) * scl + bia;
}

// ================= Kernel 2: 1x1 conv -> ckT / cvT =================
__global__ __launch_bounds__(256) void kv_kernel(
    const float* __restrict__ kv_w, const float* __restrict__ kv_b)
{
    extern __shared__ float sm2[];
    float* sW = sm2;          // [64][128]
    float* sP = sm2 + 8192;   // [128][64]
    int og = blockIdx.x, b = blockIdx.y, t = threadIdx.x;
    const float4* wsrc = (const float4*)(kv_w + og * 64 * 128);
    const float4* psrc = (const float4*)(g_p + b * 8192);
#pragma unroll
    for (int i = 0; i < 8; i++) {
        ((float4*)sW)[t + i * 256] = wsrc[t + i * 256];
        ((float4*)sP)[t + i * 256] = psrc[t + i * 256];
    }
    __syncthreads();
    int ty = t >> 4, tx = t & 15;
    float acc[4][4] = {};
#pragma unroll 4
    for (int c = 0; c < 128; c++) {
        float4 pv = ((const float4*)(sP + c * 64))[tx];
        float w0 = sW[(ty * 4 + 0) * 128 + c];
        float w1 = sW[(ty * 4 + 1) * 128 + c];
        float w2 = sW[(ty * 4 + 2) * 128 + c];
        float w3 = sW[(ty * 4 + 3) * 128 + c];
        acc[0][0] += w0 * pv.x; acc[0][1] += w0 * pv.y; acc[0][2] += w0 * pv.z; acc[0][3] += w0 * pv.w;
        acc[1][0] += w1 * pv.x; acc[1][1] += w1 * pv.y; acc[1][2] += w1 * pv.z; acc[1][3] += w1 * pv.w;
        acc[2][0] += w2 * pv.x; acc[2][1] += w2 * pv.y; acc[2][2] += w2 * pv.z; acc[2][3] += w2 * pv.w;
        acc[3][0] += w3 * pv.x; acc[3][1] += w3 * pv.y; acc[3][2] += w3 * pv.z; acc[3][3] += w3 * pv.w;
    }
#pragma unroll
    for (int i = 0; i < 4; i++) {
        int o = og * 64 + ty * 4 + i;
        float bs = kv_b[o];
#pragma unroll
        for (int j = 0; j < 4; j++) {
            int k = tx * 4 + j;
            float v = acc[i][j] + bs;
            if (o < 256) g_ckT[(b * 256 + o) * 64 + k] = v;
            else         g_cvT[(b * 64 + k) * 256 + (o - 256)] = v;
        }
    }
}

// ================= Kernel 3: persistent fused main =================
// grid 152 (1/SM), block 256, smem 216576B.
__global__ __launch_bounds__(256) void main_kernel(
    const float* __restrict__ x_l,
    const float* __restrict__ gam, const float* __restrict__ bet,
    const float* __restrict__ mu,  const float* __restrict__ var,
    const float* __restrict__ reatt,
    float* __restrict__ out)
{
    extern __shared__ float sm[];
    float* s_ck  = sm;            // ckS [c=256][k=64]  (scaled by scl*0.125)
    float* s_xl  = sm + 16384;    // raw x_l [c=256][n=64]
    float* s_cv  = sm + 32768;    // [k=64][c=256]
    float* s_att = sm + 49152;    // [k=64][n=64]
    float* s_scl = sm + 53248;    // 256
    float* s_bia = sm + 53504;    // 256
    float* s_red = sm + 53760;    // 256
    float* s_kb  = sm + 54016;    // 64
    float* s_inv = sm + 54080;    // 64

    const int t = threadIdx.x;
    const int bid = blockIdx.x;
    // 2048 tiles over 152 blocks: first 72 blocks get 14, rest 13
    const int start = bid * 13 + (bid < 72 ? bid : 72);
    const int cnt   = 13 + (bid < 72 ? 1 : 0);

    { // BN_l scale/bias (same for all batches)
        float sc = gam[t] * rsqrtf(var[t] + EPSV);
        s_scl[t] = sc;
        s_bia[t] = bet[t] - mu[t] * sc;
    }
    { // initial x_l tile (raw)
        int b0 = start >> 8, h0 = (start & 255) << 6;
        const float4* xs = (const float4*)(x_l + (long)b0 * 4194304 + h0);
#pragma unroll
        for (int i = 0; i < 16; i++) {
            int e = t + i * 256;
            ((float4*)s_xl)[e] = xs[(long)(e >> 4) * 4096 + (e & 15)];
        }
    }

    int cur_b = -1;
    for (int g = start; g < start + cnt; ++g) {
        const int b = g >> 8;
        const int hw0 = (g & 255) << 6;

        if (b != cur_b) { // restage ck/cv/kb for new batch
            cur_b = b;
            __syncthreads();
            const float4* cks = (const float4*)(g_ckT + b * 16384);
            const float4* cvs = (const float4*)(g_cvT + b * 16384);
#pragma unroll
            for (int i = 0; i < 16; i++) {
                int e = t + i * 256;
                float4 v = cks[e];
                float f = s_scl[e >> 4] * 0.125f;
                v.x *= f; v.y *= f; v.z *= f; v.w *= f;
                ((float4*)s_ck)[e] = v;
                ((float4*)s_cv)[e] = cvs[e];
            }
            { // kb partials: kb[k] = sum_c ck[c][k]*bia[c]
                int q = t >> 6, k = t & 63;
                const float* base = g_ckT + b * 16384 + k;
                float s = 0.f;
#pragma unroll 8
                for (int c = q * 64; c < q * 64 + 64; c++) s += base[c * 64] * s_bia[c];
                s_red[t] = s;
            }
            __syncthreads();
            if (t < 64)
                s_kb[t] = 0.125f * (s_red[t] + s_red[64 + t] + s_red[128 + t] + s_red[192 + t]
                                    + __ldg(reatt + t));
        }
        __syncthreads();

        // ---- Phase 2: logits[k][n] = sum_c ckS[c][k]*xl_raw[c][n] + kb[k] ----
        {
            const int ty = t >> 4, tx = t & 15;
            const float4*     ck4 = (const float4*)s_ck;
            const ulonglong2* xl2 = (const ulonglong2*)s_xl;
            ull acc[4][2] = {};
#pragma unroll 4
            for (int c = 0; c < 256; c++) {
                float4 a = ck4[c * 16 + ty];
                ulonglong2 bv = xl2[c * 16 + tx];
                ull a0 = pk2(a.x, a.x), a1 = pk2(a.y, a.y);
                ull a2 = pk2(a.z, a.z), a3 = pk2(a.w, a.w);
                acc[0][0] = ffma2(a0, bv.x, acc[0][0]); acc[0][1] = ffma2(a0, bv.y, acc[0][1]);
                acc[1][0] = ffma2(a1, bv.x, acc[1][0]); acc[1][1] = ffma2(a1, bv.y, acc[1][1]);
                acc[2][0] = ffma2(a2, bv.x, acc[2][0]); acc[2][1] = ffma2(a2, bv.y, acc[2][1]);
                acc[3][0] = ffma2(a3, bv.x, acc[3][0]); acc[3][1] = ffma2(a3, bv.y, acc[3][1]);
            }
#pragma unroll
            for (int kk = 0; kk < 4; kk++) {
                int k = ty * 4 + kk;
                float kb = s_kb[k];
                float2 p0 = upk2(acc[kk][0]), p1 = upk2(acc[kk][1]);
                float* dst = s_att + k * 64 + tx * 4;
                dst[0] = p0.x + kb; dst[1] = p0.y + kb;
                dst[2] = p1.x + kb; dst[3] = p1.y + kb;
            }
        }
        __syncthreads();

        // ---- softmax over k, parallel: 4 threads per column ----
        {
            int q = t >> 6, n = t & 63;
            float m = -3.4e38f;
#pragma unroll
            for (int k = q * 16; k < q * 16 + 16; k++) m = fmaxf(m, s_att[k * 64 + n]);
            s_red[t] = m;
            __syncthreads();
            m = fmaxf(fmaxf(s_red[n], s_red[64 + n]), fmaxf(s_red[128 + n], s_red[192 + n]));
            float s = 0.f;
#pragma unroll
            for (int k = q * 16; k < q * 16 + 16; k++) {
                float e = __expf(s_att[k * 64 + n] - m);
                s_att[k * 64 + n] = e;
                s += e;
            }
            __syncthreads();   // all max reads done before overwriting s_red
            s_red[t] = s;
            __syncthreads();
            if (t < 64)
                s_inv[t] = 1.0f / (s_red[t] + s_red[64 + t] + s_red[128 + t] + s_red[192 + t]);
        }
        __syncthreads();

        // ---- prefetch next tile's x_l into registers (hidden under phase 3) ----
        const bool has_next = (g + 1 < start + cnt);
        float4 pf[16];
        if (has_next) {
            int gn = g + 1, bn = gn >> 8, hn = (gn & 255) << 6;
            const float4* xs = (const float4*)(x_l + (long)bn * 4194304 + hn);
#pragma unroll
            for (int i = 0; i < 16; i++) {
                int e = t + i * 256;
                pf[i] = xs[(long)(e >> 4) * 4096 + (e & 15)];
            }
        }

        // ---- Phase 3: out[c][n] = xl_raw + (sum_k e[k][n]*cv[k][c]) * inv[n] ----
        {
            const int cg = t >> 2, ng = t & 3;
            const int c0 = cg * 4, n0 = ng * 16;
            ull acc[4][8] = {};
#pragma unroll 2
            for (int k = 0; k < 64; k++) {
                float4 cvv = *(const float4*)(s_cv + (k << 8) + c0);
                const ulonglong2* ap = (const ulonglong2*)(s_att + (k << 6) + n0);
                ulonglong2 q0 = ap[0], q1 = ap[1], q2 = ap[2], q3 = ap[3];
                ull d0 = pk2(cvv.x, cvv.x);
                acc[0][0] = ffma2(d0, q0.x, acc[0][0]); acc[0][1] = ffma2(d0, q0.y, acc[0][1]);
                acc[0][2] = ffma2(d0, q1.x, acc[0][2]); acc[0][3] = ffma2(d0, q1.y, acc[0][3]);
                acc[0][4] = ffma2(d0, q2.x, acc[0][4]); acc[0][5] = ffma2(d0, q2.y, acc[0][5]);
                acc[0][6] = ffma2(d0, q3.x, acc[0][6]); acc[0][7] = ffma2(d0, q3.y, acc[0][7]);
                ull d1 = pk2(cvv.y, cvv.y);
                acc[1][0] = ffma2(d1, q0.x, acc[1][0]); acc[1][1] = ffma2(d1, q0.y, acc[1][1]);
                acc[1][2] = ffma2(d1, q1.x, acc[1][2]); acc[1][3] = ffma2(d1, q1.y, acc[1][3]);
                acc[1][4] = ffma2(d1, q2.x, acc[1][4]); acc[1][5] = ffma2(d1, q2.y, acc[1][5]);
                acc[1][6] = ffma2(d1, q3.x, acc[1][6]); acc[1][7] = ffma2(d1, q3.y, acc[1][7]);
                ull d2 = pk2(cvv.z, cvv.z);
                acc[2][0] = ffma2(d2, q0.x, acc[2][0]); acc[2][1] = ffma2(d2, q0.y, acc[2][1]);
                acc[2][2] = ffma2(d2, q1.x, acc[2][2]); acc[2][3] = ffma2(d2, q1.y, acc[2][3]);
                acc[2][4] = ffma2(d2, q2.x, acc[2][4]); acc[2][5] = ffma2(d2, q2.y, acc[2][5]);
                acc[2][6] = ffma2(d2, q3.x, acc[2][6]); acc[2][7] = ffma2(d2, q3.y, acc[2][7]);
                ull d3 = pk2(cvv.w, cvv.w);
                acc[3][0] = ffma2(d3, q0.x, acc[3][0]); acc[3][1] = ffma2(d3, q0.y, acc[3][1]);
                acc[3][2] = ffma2(d3, q1.x, acc[3][2]); acc[3][3] = ffma2(d3, q1.y, acc[3][3]);
                acc[3][4] = ffma2(d3, q2.x, acc[3][4]); acc[3][5] = ffma2(d3, q2.y, acc[3][5]);
                acc[3][6] = ffma2(d3, q3.x, acc[3][6]); acc[3][7] = ffma2(d3, q3.y, acc[3][7]);
            }
            long gbase = (long)b * 4194304 + hw0 + n0;
#pragma unroll
            for (int cc = 0; cc < 4; cc++) {
                int c = c0 + cc;
                const float4* xs = (const float4*)(s_xl + c * 64 + n0);
                float4*       og = (float4*)(out + gbase + (long)c * 16384);
#pragma unroll
                for (int q = 0; q < 4; q++) {
                    float4 xv = xs[q];
                    float2 r0 = upk2(acc[cc][q * 2]);
                    float2 r1 = upk2(acc[cc][q * 2 + 1]);
                    int nb = n0 + q * 4;
                    float4 o;
                    o.x = xv.x + r0.x * s_inv[nb + 0];
                    o.y = xv.y + r0.y * s_inv[nb + 1];
                    o.z = xv.z + r1.x * s_inv[nb + 2];
                    o.w = xv.w + r1.y * s_inv[nb + 3];
                    og[q] = o;
                }
            }
        }
        __syncthreads();   // s_xl fully consumed by epilogue
        if (has_next) {
#pragma unroll
            for (int i = 0; i < 16; i++) {
                int e = t + i * 256;
                ((float4*)s_xl)[e] = pf[i];
            }
        }
    }
}

// ============================================================
extern "C" void kernel_launch(void* const* d_in, const int* in_sizes, int n_in,
                              void* d_out, int out_size)
{
    const float* x_h   = (const float*)d_in[0];
    const float* x_l   = (const float*)d_in[1];
    const float* bhg   = (const float*)d_in[2];
    const float* bhb   = (const float*)d_in[3];
    const float* bhm   = (const float*)d_in[4];
    const float* bhv   = (const float*)d_in[5];
    const float* kvw   = (const float*)d_in[6];
    const float* kvb   = (const float*)d_in[7];
    const float* blg   = (const float*)d_in[8];
    const float* blb   = (const float*)d_in[9];
    const float* blm   = (const float*)d_in[10];
    const float* blv   = (const float*)d_in[11];
    const float* reatt = (const float*)d_in[12];
    float* out = (float*)d_out;

    cudaFuncSetAttribute(kv_kernel,   cudaFuncAttributeMaxDynamicSharedMemorySize, 65536);
    cudaFuncSetAttribute(main_kernel, cudaFuncAttributeMaxDynamicSharedMemorySize, 216576);

    pool_kernel<<<256, 256>>>(x_h, bhg, bhb, bhm, bhv);
    kv_kernel<<<dim3(8, 8), 256, 65536>>>(kvw, kvb);
    main_kernel<<<152, 256, 216576>>>(x_l, blg, blb, blm, blv, reatt, out);
}

// round 9
// speedup vs baseline: 1.9836x; 1.7797x over previous
#include <cuda_runtime.h>
#include <cuda_bf16.h>
#include <cstdint>

#define EPSV 1e-5f

// ---- smem map (bytes), all tiles XOR-swizzled (chunk16B ^= row&7) ----
#define XL_O   0            // [256 c][64 n] bf16 hi, pitch 128B
#define XL_LO  32768
#define CK_O   65536        // [64 k][256 c] bf16 hi, pitch 512B
#define CK_LO  98304
#define CV_O   131072       // [256 c][64 k] bf16 hi, pitch 128B
#define CV_LO  163840
#define ATT_O  196608       // [64 k][64 n] bf16 hi, pitch 128B
#define ATT_LO 204800
#define WMAX_O 212992       // [4][64] f32
#define WSUM_O 214016       // [4][64] f32
#define KB_O   215040       // [64] f32
#define INV_O  215296       // [64] f32
#define SMEMSZ 215552

__device__ float g_p[8 * 128 * 64];
__device__ float g_ck[8 * 64 * 256];   // [b][k][c]
__device__ float g_cv[8 * 256 * 64];   // [b][c][k]

__device__ __forceinline__ uint32_t s2u(const void* p) {
    uint32_t a; asm("{.reg .u64 t; cvta.to.shared.u64 t,%1; cvt.u32.u64 %0,t;}" : "=r"(a) : "l"(p)); return a;
}
__device__ __forceinline__ void ldsm4(uint32_t* r, uint32_t a) {
    asm volatile("ldmatrix.sync.aligned.m8n8.x4.shared.b16 {%0,%1,%2,%3},[%4];"
                 : "=r"(r[0]), "=r"(r[1]), "=r"(r[2]), "=r"(r[3]) : "r"(a));
}
__device__ __forceinline__ void ldsm4t(uint32_t* r, uint32_t a) {
    asm volatile("ldmatrix.sync.aligned.m8n8.x4.trans.shared.b16 {%0,%1,%2,%3},[%4];"
                 : "=r"(r[0]), "=r"(r[1]), "=r"(r[2]), "=r"(r[3]) : "r"(a));
}
__device__ __forceinline__ void hmma(float* d, const uint32_t* a, const uint32_t* b) {
    asm volatile("mma.sync.aligned.m16n8k16.row.col.f32.bf16.bf16.f32 "
                 "{%0,%1,%2,%3},{%4,%5,%6,%7},{%8,%9},{%0,%1,%2,%3};"
                 : "+f"(d[0]), "+f"(d[1]), "+f"(d[2]), "+f"(d[3])
                 : "r"(a[0]), "r"(a[1]), "r"(a[2]), "r"(a[3]), "r"(b[0]), "r"(b[1]));
}
__device__ __forceinline__ uint32_t bpack(float x, float y) {
    __nv_bfloat162 h = __floats2bfloat162_rn(x, y);
    return *(uint32_t*)&h;
}
__device__ __forceinline__ float2 bunpack(uint32_t u) {
    __nv_bfloat162 h = *(__nv_bfloat162*)&u;
    return __bfloat1622float2(h);
}

// ================= Kernel 1: BN(x_h) + 8x8 maxpool =================
__global__ __launch_bounds__(256) void pool_kernel(
    const float* __restrict__ x_h, const float* __restrict__ gam, const float* __restrict__ bet,
    const float* __restrict__ mu, const float* __restrict__ var)
{
    int idx = blockIdx.x * 256 + threadIdx.x;
    int k = idx & 63, c = (idx >> 6) & 127, b = idx >> 13;
    float scl = gam[c] * rsqrtf(var[c] + EPSV);
    float bia = bet[c] - mu[c] * scl;
    const float* base = x_h + ((((b * 128 + c) * 64) + (k >> 3) * 8) * 64) + (k & 7) * 8;
    float mx = -3.4e38f, mn = 3.4e38f;
#pragma unroll
    for (int r = 0; r < 8; r++) {
        const float4* p4 = (const float4*)(base + r * 64);
        float4 a = p4[0], d = p4[1];
        mx = fmaxf(mx, fmaxf(fmaxf(a.x, a.y), fmaxf(a.z, a.w)));
        mx = fmaxf(mx, fmaxf(fmaxf(d.x, d.y), fmaxf(d.z, d.w)));
        mn = fminf(mn, fminf(fminf(a.x, a.y), fminf(a.z, a.w)));
        mn = fminf(mn, fminf(fminf(d.x, d.y), fminf(d.z, d.w)));
    }
    g_p[idx] = ((scl >= 0.f) ? mx : mn) * scl + bia;
}

// ================= Kernel 2: 1x1 conv -> g_ck [b][k][c] / g_cv [b][c][k] ==========
__global__ __launch_bounds__(256) void kv_kernel(
    const float* __restrict__ kv_w, const float* __restrict__ kv_b)
{
    extern __shared__ float sm2[];
    float* sW = sm2; float* sP = sm2 + 8192;
    int og = blockIdx.x, b = blockIdx.y, t = threadIdx.x;
    const float4* wsrc = (const float4*)(kv_w + og * 64 * 128);
    const float4* psrc = (const float4*)(g_p + b * 8192);
#pragma unroll
    for (int i = 0; i < 8; i++) {
        ((float4*)sW)[t + i * 256] = wsrc[t + i * 256];
        ((float4*)sP)[t + i * 256] = psrc[t + i * 256];
    }
    __syncthreads();
    int ty = t >> 4, tx = t & 15;
    float acc[4][4] = {};
#pragma unroll 4
    for (int c = 0; c < 128; c++) {
        float4 pv = ((const float4*)(sP + c * 64))[tx];
#pragma unroll
        for (int i = 0; i < 4; i++) {
            float w = sW[(ty * 4 + i) * 128 + c];
            acc[i][0] += w * pv.x; acc[i][1] += w * pv.y;
            acc[i][2] += w * pv.z; acc[i][3] += w * pv.w;
        }
    }
#pragma unroll
    for (int i = 0; i < 4; i++) {
        int o = og * 64 + ty * 4 + i;
        float bs = kv_b[o];
#pragma unroll
        for (int j = 0; j < 4; j++) {
            int k = tx * 4 + j;
            float v = acc[i][j] + bs;
            if (o < 256) g_ck[(b * 64 + k) * 256 + o] = v;
            else         g_cv[(b * 256 + (o - 256)) * 64 + k] = v;
        }
    }
}

// ================= Kernel 3: persistent HMMA main =================
__global__ __launch_bounds__(256) void main_kernel(
    const float* __restrict__ x_l,
    const float* __restrict__ gam, const float* __restrict__ bet,
    const float* __restrict__ mu,  const float* __restrict__ var,
    const float* __restrict__ reatt, float* __restrict__ out)
{
    extern __shared__ __align__(128) char smc[];
    const uint32_t smb = s2u(smc);
    float* WMAX = (float*)(smc + WMAX_O);
    float* WSUM = (float*)(smc + WSUM_O);
    float* KB   = (float*)(smc + KB_O);
    float* INV  = (float*)(smc + INV_O);

    const int t = threadIdx.x, w = t >> 5, lane = t & 31;
    const int g8 = lane >> 2, tid4 = lane & 3;   // mma group / thread-in-group
    const int r8 = lane & 7, i4 = lane >> 3;     // ldmatrix row / tile index
    const int bid = blockIdx.x;
    const int start = bid * 13 + (bid < 72 ? bid : 72);
    const int cnt = 13 + (bid < 72 ? 1 : 0);

    const int m0_2 = (w >> 1) * 16;   // phase2: k-row base
    const int n0_2 = (w & 1) * 32;    // phase2: n base
    const int m0_3 = w * 32;          // phase3: c base

    // preload first tile's x_l into registers
    float4 pf[16];
    {
        int b0 = start >> 8, h0 = (start & 255) << 6;
        const float4* xs = (const float4*)(x_l + (long)b0 * 4194304 + h0);
#pragma unroll
        for (int i = 0; i < 16; i++) { int e = t + i * 256; pf[i] = __ldg(&xs[(long)(e >> 4) * 4096 + (e & 15)]); }
    }
    bool pf_valid = true;
    int cur_b = -1;

    for (int g = start; g < start + cnt; ++g) {
        const int b = g >> 8, hw0 = (g & 255) << 6;

        // ---- commit prefetched x_l -> XL hi/lo (swizzled) ----
        if (pf_valid) {
#pragma unroll
            for (int i = 0; i < 16; i++) {
                int e = t + i * 256, c = e >> 4, n4 = e & 15;
                float4 v = pf[i];
                uint32_t h01 = bpack(v.x, v.y), h23 = bpack(v.z, v.w);
                float2 f01 = bunpack(h01), f23 = bunpack(h23);
                uint32_t l01 = bpack(v.x - f01.x, v.y - f01.y);
                uint32_t l23 = bpack(v.z - f23.x, v.w - f23.y);
                int off = c * 128 + (((n4 >> 1) ^ (c & 7)) << 4) + (n4 & 1) * 8;
                *(uint2*)(smc + XL_O + off)  = make_uint2(h01, h23);
                *(uint2*)(smc + XL_LO + off) = make_uint2(l01, l23);
            }
            pf_valid = false;
        }

        // ---- per-batch restage: ck (BN-scaled, split), cv (split), kb ----
        if (b != cur_b) {
            cur_b = b;
            __syncthreads();
            float* SCL = (float*)(smc + ATT_O);         // alias att region
            float* BIA = (float*)(smc + ATT_O + 1024);
            float sc = gam[t] * rsqrtf(var[t] + EPSV);
            SCL[t] = sc; BIA[t] = bet[t] - mu[t] * sc;
            __syncthreads();
            {   // ck: thread -> (k = t>>2, 64 c's)
                int k = t >> 2, cq = (t & 3) * 64;
                const float* src = g_ck + (b * 64 + k) * 256;
#pragma unroll 4
                for (int cc = 0; cc < 64; cc += 4) {
                    int c = cq + cc;
                    float4 v = *(const float4*)(src + c);
                    v.x *= SCL[c] * 0.125f;   v.y *= SCL[c+1] * 0.125f;
                    v.z *= SCL[c+2] * 0.125f; v.w *= SCL[c+3] * 0.125f;
                    uint32_t h01 = bpack(v.x, v.y), h23 = bpack(v.z, v.w);
                    float2 f01 = bunpack(h01), f23 = bunpack(h23);
                    uint32_t l01 = bpack(v.x - f01.x, v.y - f01.y);
                    uint32_t l23 = bpack(v.z - f23.x, v.w - f23.y);
                    int off = k * 512 + (((c >> 3) ^ (k & 7)) << 4) + (c & 7) * 2;
                    *(uint2*)(smc + CK_O + off)  = make_uint2(h01, h23);
                    *(uint2*)(smc + CK_LO + off) = make_uint2(l01, l23);
                }
            }
            {   // cv: thread -> row c = t, 64 k's
                const float* sv = g_cv + (b * 256 + t) * 64;
#pragma unroll 4
                for (int k = 0; k < 64; k += 4) {
                    float4 v = *(const float4*)(sv + k);
                    uint32_t h01 = bpack(v.x, v.y), h23 = bpack(v.z, v.w);
                    float2 f01 = bunpack(h01), f23 = bunpack(h23);
                    uint32_t l01 = bpack(v.x - f01.x, v.y - f01.y);
                    uint32_t l23 = bpack(v.z - f23.x, v.w - f23.y);
                    int off = t * 128 + (((k >> 3) ^ (t & 7)) << 4) + (k & 7) * 2;
                    *(uint2*)(smc + CV_O + off)  = make_uint2(h01, h23);
                    *(uint2*)(smc + CV_LO + off) = make_uint2(l01, l23);
                }
            }
            {   // kb[k] = 0.125*(sum_c ck[k][c]*BIA[c] + reatt[k])
                int kk = t & 63, q = t >> 6;
                const float* bp = g_ck + (b * 64 + kk) * 256 + q * 64;
                float s = 0.f;
#pragma unroll 16
                for (int c = 0; c < 64; c++) s += bp[c] * BIA[q * 64 + c];
                WMAX[q * 64 + kk] = s;
            }
            __syncthreads();
            if (t < 64) KB[t] = 0.125f * (WMAX[t] + WMAX[64 + t] + WMAX[128 + t] + WMAX[192 + t] + __ldg(reatt + t));
        }
        __syncthreads();

        // ================= Phase 2: logits = ck^T * xl (3 passes) =================
        float d2[4][4] = {};
        {
            const int arow = m0_2 + r8 + 8 * (i4 & 1);
            const int bro  = r8 + 8 * (i4 & 1);
            const int nch0 = (n0_2 >> 3) + (i4 >> 1);
#pragma unroll 1
            for (int pass = 0; pass < 3; pass++) {
                uint32_t ab = smb + (pass == 1 ? CK_LO : CK_O) + arow * 512;
                uint32_t bb = smb + (pass == 2 ? XL_LO : XL_O);
#pragma unroll
                for (int s = 0; s < 16; s++) {
                    uint32_t a[4], b0[4], b1[4];
                    ldsm4(a, ab + (((s * 2 + (i4 >> 1)) ^ r8) << 4));
                    uint32_t br = bb + (s * 16 + bro) * 128;
                    ldsm4t(b0, br + ((nch0 ^ r8) << 4));
                    ldsm4t(b1, br + (((nch0 + 2) ^ r8) << 4));
                    hmma(d2[0], a, b0); hmma(d2[1], a, b0 + 2);
                    hmma(d2[2], a, b1); hmma(d2[3], a, b1 + 2);
                }
            }
        }

        // ================= softmax (register-resident) =================
        {
            float kb0 = KB[m0_2 + g8], kb1 = KB[m0_2 + g8 + 8];
            float cm[4][2];
#pragma unroll
            for (int ns = 0; ns < 4; ns++) {
                d2[ns][0] += kb0; d2[ns][1] += kb0;
                d2[ns][2] += kb1; d2[ns][3] += kb1;
                cm[ns][0] = fmaxf(d2[ns][0], d2[ns][2]);
                cm[ns][1] = fmaxf(d2[ns][1], d2[ns][3]);
            }
#pragma unroll
            for (int st = 4; st < 32; st <<= 1)
#pragma unroll
                for (int ns = 0; ns < 4; ns++) {
                    cm[ns][0] = fmaxf(cm[ns][0], __shfl_xor_sync(0xffffffffu, cm[ns][0], st));
                    cm[ns][1] = fmaxf(cm[ns][1], __shfl_xor_sync(0xffffffffu, cm[ns][1], st));
                }
            if (g8 == 0)
#pragma unroll
                for (int ns = 0; ns < 4; ns++) {
                    int n = n0_2 + ns * 8 + tid4 * 2;
                    WMAX[(w >> 1) * 64 + n] = cm[ns][0];
                    WMAX[(w >> 1) * 64 + n + 1] = cm[ns][1];
                }
            __syncthreads();
            if (t < 64) WMAX[t] = fmaxf(fmaxf(WMAX[t], WMAX[64 + t]), fmaxf(WMAX[128 + t], WMAX[192 + t]));
            __syncthreads();

            float sm_[4][2];
            int k0r = m0_2 + g8;
#pragma unroll
            for (int ns = 0; ns < 4; ns++) {
                int n = n0_2 + ns * 8 + tid4 * 2;
                float c0 = WMAX[n], c1 = WMAX[n + 1];
                float e00 = __expf(d2[ns][0] - c0), e01 = __expf(d2[ns][1] - c1);
                float e10 = __expf(d2[ns][2] - c0), e11 = __expf(d2[ns][3] - c1);
                sm_[ns][0] = e00 + e10; sm_[ns][1] = e01 + e11;
                uint32_t h0 = bpack(e00, e01); float2 f0 = bunpack(h0);
                uint32_t l0 = bpack(e00 - f0.x, e01 - f0.y);
                uint32_t h1 = bpack(e10, e11); float2 f1 = bunpack(h1);
                uint32_t l1 = bpack(e10 - f1.x, e11 - f1.y);
                int off0 = k0r * 128 + ((((n >> 3)) ^ g8) << 4) + (n & 7) * 2;
                int off1 = off0 + 8 * 128;
                *(uint32_t*)(smc + ATT_O + off0)  = h0;
                *(uint32_t*)(smc + ATT_LO + off0) = l0;
                *(uint32_t*)(smc + ATT_O + off1)  = h1;
                *(uint32_t*)(smc + ATT_LO + off1) = l1;
            }
#pragma unroll
            for (int st = 4; st < 32; st <<= 1)
#pragma unroll
                for (int ns = 0; ns < 4; ns++) {
                    sm_[ns][0] += __shfl_xor_sync(0xffffffffu, sm_[ns][0], st);
                    sm_[ns][1] += __shfl_xor_sync(0xffffffffu, sm_[ns][1], st);
                }
            if (g8 == 0)
#pragma unroll
                for (int ns = 0; ns < 4; ns++) {
                    int n = n0_2 + ns * 8 + tid4 * 2;
                    WSUM[(w >> 1) * 64 + n] = sm_[ns][0];
                    WSUM[(w >> 1) * 64 + n + 1] = sm_[ns][1];
                }
            __syncthreads();
            if (t < 64) INV[t] = 1.f / (WSUM[t] + WSUM[64 + t] + WSUM[128 + t] + WSUM[192 + t]);
            __syncthreads();
        }

        // ================= Phase 3: out-acc = cv * att (3 passes) =================
        float d3[2][8][4] = {};
        {
            const int bro = r8 + 8 * (i4 & 1);
            const int aro = r8 + 8 * (i4 & 1);
#pragma unroll 1
            for (int pass = 0; pass < 3; pass++) {
                uint32_t ab = smb + (pass == 1 ? CV_LO : CV_O);
                uint32_t bb = smb + (pass == 2 ? ATT_LO : ATT_O);
#pragma unroll
                for (int ks = 0; ks < 4; ks++) {
                    uint32_t bfr[4][4];
                    uint32_t br = bb + (ks * 16 + bro) * 128;
#pragma unroll
                    for (int nq = 0; nq < 4; nq++)
                        ldsm4t(bfr[nq], br + (((nq * 2 + (i4 >> 1)) ^ r8) << 4));
#pragma unroll
                    for (int ms = 0; ms < 2; ms++) {
                        uint32_t a[4];
                        ldsm4(a, ab + (m0_3 + ms * 16 + aro) * 128 + (((ks * 2 + (i4 >> 1)) ^ r8) << 4));
#pragma unroll
                        for (int nq = 0; nq < 4; nq++) {
                            hmma(d3[ms][nq * 2], a, bfr[nq]);
                            hmma(d3[ms][nq * 2 + 1], a, bfr[nq] + 2);
                        }
                    }
                }
            }
        }

        // ---- prefetch next tile's x_l (hidden under epilogue) ----
        const bool has_next = (g + 1 < start + cnt);
        if (has_next) {
            int gn = g + 1, bn = gn >> 8, hn = (gn & 255) << 6;
            const float4* xs = (const float4*)(x_l + (long)bn * 4194304 + hn);
#pragma unroll
            for (int i = 0; i < 16; i++) { int e = t + i * 256; pf[i] = __ldg(&xs[(long)(e >> 4) * 4096 + (e & 15)]); }
            pf_valid = true;
        }

        // ================= epilogue: residual + 1/sum, direct STG =================
        {
            long gb = (long)b * 4194304 + hw0;
#pragma unroll
            for (int ms = 0; ms < 2; ms++) {
                int c0r = m0_3 + ms * 16 + g8, c1r = c0r + 8;
#pragma unroll
                for (int nq2 = 0; nq2 < 8; nq2++) {
                    int n = nq2 * 8 + tid4 * 2;
                    float2 iv = *(float2*)(INV + n);
                    int sw = (((n >> 3)) ^ g8) << 4;
                    int o0 = c0r * 128 + sw + (n & 7) * 2;
                    int o1 = c1r * 128 + sw + (n & 7) * 2;
                    float2 h0 = bunpack(*(uint32_t*)(smc + XL_O + o0));
                    float2 l0 = bunpack(*(uint32_t*)(smc + XL_LO + o0));
                    float2 h1 = bunpack(*(uint32_t*)(smc + XL_O + o1));
                    float2 l1 = bunpack(*(uint32_t*)(smc + XL_LO + o1));
                    float2 r0, r1;
                    r0.x = h0.x + l0.x + d3[ms][nq2][0] * iv.x;
                    r0.y = h0.y + l0.y + d3[ms][nq2][1] * iv.y;
                    r1.x = h1.x + l1.x + d3[ms][nq2][2] * iv.x;
                    r1.y = h1.y + l1.y + d3[ms][nq2][3] * iv.y;
                    *(float2*)(out + gb + (long)c0r * 16384 + n) = r0;
                    *(float2*)(out + gb + (long)c1r * 16384 + n) = r1;
                }
            }
        }
        __syncthreads();
    }
}

// ============================================================
extern "C" void kernel_launch(void* const* d_in, const int* in_sizes, int n_in,
                              void* d_out, int out_size)
{
    const float* x_h = (const float*)d_in[0];
    const float* x_l = (const float*)d_in[1];
    const float* bhg = (const float*)d_in[2];
    const float* bhb = (const float*)d_in[3];
    const float* bhm = (const float*)d_in[4];
    const float* bhv = (const float*)d_in[5];
    const float* kvw = (const float*)d_in[6];
    const float* kvb = (const float*)d_in[7];
    const float* blg = (const float*)d_in[8];
    const float* blb = (const float*)d_in[9];
    const float* blm = (const float*)d_in[10];
    const float* blv = (const float*)d_in[11];
    const float* reatt = (const float*)d_in[12];
    float* out = (float*)d_out;

    cudaFuncSetAttribute(kv_kernel,   cudaFuncAttributeMaxDynamicSharedMemorySize, 65536);
    cudaFuncSetAttribute(main_kernel, cudaFuncAttributeMaxDynamicSharedMemorySize, SMEMSZ);

    pool_kernel<<<256, 256>>>(x_h, bhg, bhb, bhm, bhv);
    kv_kernel<<<dim3(8, 8), 256, 65536>>>(kvw, kvb);
    main_kernel<<<152, 256, SMEMSZ>>>(x_l, blg, blb, blm, blv, reatt, out);
}